// round 6
// baseline (speedup 1.0000x reference)
#include <cuda_runtime.h>

// LIF scan over T=8 timesteps, N = 4,194,304 independent spatial elements.
//   mem = mem*0.25*(1-spike) + x[t]; spike = (mem >= 0.5)
// Pure streaming: 128 MiB read + 128 MiB write, zero reuse -> DRAM-bound.
//
// R6: ILP experiment. R3 shape confirmed reproducible (43.5 us twice);
// occupancy/launch/store-policy all proven non-binding. Last lever: deeper
// per-thread MLP. Each thread now owns TWO adjacent float4 columns ->
// 16 front-batched __ldcs loads (MLP=16), half the grid. Loads within a
// warp remain fully coalesced (lanes cover 2x512B contiguous per t).

#define DECAY  0.25f
#define THRESH 0.5f

static constexpr int T = 8;

__device__ __forceinline__ void lif_step(float4& mem, float4& spike, const float4 xv)
{
    mem.x = mem.x * (DECAY * (1.0f - spike.x)) + xv.x;
    mem.y = mem.y * (DECAY * (1.0f - spike.y)) + xv.y;
    mem.z = mem.z * (DECAY * (1.0f - spike.z)) + xv.z;
    mem.w = mem.w * (DECAY * (1.0f - spike.w)) + xv.w;
    spike.x = (mem.x >= THRESH) ? 1.0f : 0.0f;
    spike.y = (mem.y >= THRESH) ? 1.0f : 0.0f;
    spike.z = (mem.z >= THRESH) ? 1.0f : 0.0f;
    spike.w = (mem.w >= THRESH) ? 1.0f : 0.0f;
}

__global__ __launch_bounds__(256) void lif_scan_kernel(
    const float4* __restrict__ x, float4* __restrict__ out, int n4)
{
    // Thread handles columns iA = 2*gid_blockpart and iB = iA + blockDim.x,
    // keeping each warp's per-load footprint contiguous (512B per access).
    const int base = blockIdx.x * (2 * blockDim.x) + threadIdx.x;
    const int iA = base;
    const int iB = base + blockDim.x;
    if (iB >= n4) {
        // Tail (never taken for this problem size since n4 % 512 == 0, but safe).
        if (iA < n4) {
            float4 mem = make_float4(0.f,0.f,0.f,0.f), spike = make_float4(0.f,0.f,0.f,0.f);
#pragma unroll
            for (int t = 0; t < T; t++) {
                float4 xv = __ldcs(&x[(size_t)t * n4 + iA]);
                lif_step(mem, spike, xv);
                __stcs(&out[(size_t)t * n4 + iA], spike);
            }
        }
        return;
    }

    // 16 independent streaming loads front-batched: MLP=16.
    float4 xa[T], xb[T];
#pragma unroll
    for (int t = 0; t < T; t++) {
        xa[t] = __ldcs(&x[(size_t)t * n4 + iA]);
        xb[t] = __ldcs(&x[(size_t)t * n4 + iB]);
    }

    float4 memA = make_float4(0.f,0.f,0.f,0.f), spikeA = make_float4(0.f,0.f,0.f,0.f);
    float4 memB = make_float4(0.f,0.f,0.f,0.f), spikeB = make_float4(0.f,0.f,0.f,0.f);

#pragma unroll
    for (int t = 0; t < T; t++) {
        lif_step(memA, spikeA, xa[t]);
        lif_step(memB, spikeB, xb[t]);
        __stcs(&out[(size_t)t * n4 + iA], spikeA);
        __stcs(&out[(size_t)t * n4 + iB], spikeB);
    }
}

extern "C" void kernel_launch(void* const* d_in, const int* in_sizes, int n_in,
                              void* d_out, int out_size)
{
    const float* x = (const float*)d_in[0];
    float* out = (float*)d_out;

    const int total = in_sizes[0];       // T * N
    const int n = total / T;             // elements per timestep (4,194,304)
    const int n4 = n / 4;                // float4 count per timestep (1,048,576)

    const int threads = 256;
    const int per_block = 2 * threads;   // 2 float4 columns per thread
    const int blocks = (n4 + per_block - 1) / per_block;  // 2048

    lif_scan_kernel<<<blocks, threads>>>(
        (const float4*)x, (float4*)out, n4);
}

// round 7
// speedup vs baseline: 1.0065x; 1.0065x over previous
#include <cuda_runtime.h>

// LIF scan over T=8 timesteps, N = 4,194,304 independent spatial elements.
//   mem = mem*0.25*(1-spike) + x[t]; spike = (mem >= 0.5)
// Pure streaming: 128 MiB read + 128 MiB write, zero reuse -> DRAM-bound.
//
// FINAL (R3 shape, confirmed 43.5 us twice). Lever sweep R1-R6 proved the
// kernel is pinned at the HBM roofline (~5.85 TB/s for a balanced R/W
// stream, ncu dur ~36 us invariant): occupancy 32-84%, MLP 8-16, flat vs
// persistent grid, and store policy (.cs/.wt/default) all non-binding.
// Shape: flat one-float4-per-thread, 8 front-batched __ldcs loads (MLP=8),
// __stcs stores (evict-first both ways; zero reuse).

#define DECAY  0.25f
#define THRESH 0.5f

static constexpr int T = 8;

__global__ __launch_bounds__(256) void lif_scan_kernel(
    const float4* __restrict__ x, float4* __restrict__ out, int n4)
{
    int i = blockIdx.x * blockDim.x + threadIdx.x;
    if (i >= n4) return;

    // 8 independent streaming loads (evict-first: zero reuse), MLP=8.
    float4 xv[T];
#pragma unroll
    for (int t = 0; t < T; t++) {
        xv[t] = __ldcs(&x[(size_t)t * n4 + i]);
    }

    float4 mem   = make_float4(0.f, 0.f, 0.f, 0.f);
    float4 spike = make_float4(0.f, 0.f, 0.f, 0.f);

#pragma unroll
    for (int t = 0; t < T; t++) {
        mem.x = mem.x * (DECAY * (1.0f - spike.x)) + xv[t].x;
        mem.y = mem.y * (DECAY * (1.0f - spike.y)) + xv[t].y;
        mem.z = mem.z * (DECAY * (1.0f - spike.z)) + xv[t].z;
        mem.w = mem.w * (DECAY * (1.0f - spike.w)) + xv[t].w;
        spike.x = (mem.x >= THRESH) ? 1.0f : 0.0f;
        spike.y = (mem.y >= THRESH) ? 1.0f : 0.0f;
        spike.z = (mem.z >= THRESH) ? 1.0f : 0.0f;
        spike.w = (mem.w >= THRESH) ? 1.0f : 0.0f;
        __stcs(&out[(size_t)t * n4 + i], spike);
    }
}

extern "C" void kernel_launch(void* const* d_in, const int* in_sizes, int n_in,
                              void* d_out, int out_size)
{
    const float* x = (const float*)d_in[0];
    float* out = (float*)d_out;

    const int total = in_sizes[0];       // T * N
    const int n = total / T;             // elements per timestep (4,194,304)
    const int n4 = n / 4;                // float4 count per timestep (1,048,576)

    const int threads = 256;
    const int blocks = (n4 + threads - 1) / threads;

    lif_scan_kernel<<<blocks, threads>>>(
        (const float4*)x, (float4*)out, n4);
}